// round 5
// baseline (speedup 1.0000x reference)
#include <cuda_runtime.h>
#include <cuda_fp16.h>
#include <cstdint>
#include <cstddef>

#define CHANNELS 1024
#define PIVOT 16384

// tcgen05 is arch-SPECIFIC (sm_103a). The harness also compiles a non-'a'
// compute_103 PTX pass; give it a plain-CUDA fallback body.
#if defined(__CUDA_ARCH_FEAT_SM103_ALL) || defined(__CUDA_ARCH_FEAT_SM100_ALL) || defined(__CUDA_ARCH_SPECIFIC__)
#define HAS_TCGEN05 1
#else
#define HAS_TCGEN05 0
#endif

// ---------------- scratch (static device arrays are allowed) ----------
__device__ __half Xh_g[(size_t)PIVOT * CHANNELS];        // 32 MB
__device__ __half Wh_g[(size_t)CHANNELS * CHANNELS];     //  2 MB
__device__ __half A2_g[(size_t)2 * PIVOT * CHANNELS];    // 64 MB (deinterleaved J)

// ---------------- helpers ----------------
__device__ __forceinline__ uint32_t smem_u32(const void* p) {
    uint32_t r;
    asm("{ .reg .u64 t; cvta.to.shared.u64 t, %1; cvt.u32.u64 %0, t; }" : "=r"(r) : "l"(p));
    return r;
}
__device__ __forceinline__ void cp_async16(uint32_t d, const void* s) {
    asm volatile("cp.async.cg.shared.global [%0], [%1], 16;" :: "r"(d), "l"(s));
}
__device__ __forceinline__ void cp_commit() { asm volatile("cp.async.commit_group;"); }
template<int N> __device__ __forceinline__ void cp_wait() {
    asm volatile("cp.async.wait_group %0;" :: "n"(N));
}
#define SW128(x) ((x) ^ (((x) >> 3) & 0x70))

// SW128 K-major smem descriptor (layout=2, version=1, SBO=64, LBO=1)
__device__ __forceinline__ uint64_t make_desc(uint32_t addr) {
    const uint64_t base = (uint64_t(2) << 61) | (uint64_t(1) << 46)
                        | (uint64_t(64) << 32) | (uint64_t(1) << 16);
    return base | ((uint64_t)(addr >> 4) & 0x3FFF);
}

#if HAS_TCGEN05
__device__ __forceinline__ uint32_t ctarank() {
    uint32_t r; asm("mov.u32 %0, %%cluster_ctarank;" : "=r"(r)); return r;
}
#define TCG_ALLOC_CG2(smem_res, ncols) \
    asm volatile("tcgen05.alloc.cta_group::2.sync.aligned.shared::cta.b32 [%0], %1;" \
                 :: "r"(smem_res), "r"((uint32_t)(ncols)) : "memory")
#define TCG_DEALLOC_CG2(tmem, ncols) \
    asm volatile("tcgen05.dealloc.cta_group::2.sync.aligned.b32 %0, %1;" \
                 :: "r"(tmem), "r"((uint32_t)(ncols)))
#define TCG_RELINQ_CG2() \
    asm volatile("tcgen05.relinquish_alloc_permit.cta_group::2.sync.aligned;")
#define TCG_COMMIT_MC(mbar) \
    asm volatile("tcgen05.commit.cta_group::2.mbarrier::arrive::one.shared::cluster.multicast::cluster.b64 [%0], %1;" \
                 :: "r"(mbar), "h"((uint16_t)3) : "memory")
#define TCG_FENCE_AFTER()  asm volatile("tcgen05.fence::after_thread_sync;" ::: "memory")
#define TCG_FENCE_BEFORE() asm volatile("tcgen05.fence::before_thread_sync;" ::: "memory")
#define TCG_WAIT_LD()      asm volatile("tcgen05.wait::ld.sync.aligned;" ::: "memory")
#define FENCE_ASYNC()      asm volatile("fence.proxy.async.shared::cta;" ::: "memory")
#define MBAR_INIT(addr, cnt) \
    asm volatile("mbarrier.init.shared.b64 [%0], %1;" :: "r"(addr), "r"((uint32_t)(cnt)) : "memory")
#define MBAR_INVAL(addr) \
    asm volatile("mbarrier.inval.shared.b64 [%0];" :: "r"(addr) : "memory")
#define CLUSTER_SYNC() do { \
    asm volatile("barrier.cluster.arrive.aligned;" ::: "memory"); \
    asm volatile("barrier.cluster.wait.aligned;"   ::: "memory"); } while (0)

// arrive (release, cluster scope) on leader CTA's mbarrier at same smem offset
__device__ __forceinline__ void arrive_leader(uint32_t addr) {
    asm volatile(
        "{\n\t.reg .b32 ra;\n\t"
        "mapa.shared::cluster.u32 ra, %0, 0;\n\t"
        "mbarrier.arrive.release.cluster.shared::cluster.b64 _, [ra];\n\t}"
        :: "r"(addr) : "memory");
}
__device__ __forceinline__ void mbar_wait(uint32_t addr, uint32_t parity) {
    asm volatile(
        "{\n\t.reg .pred P;\n\t"
        "W_%=:\n\t"
        "mbarrier.try_wait.parity.shared.b64 P, [%0], %1;\n\t"
        "@!P bra W_%=;\n\t}"
        :: "r"(addr), "r"(parity) : "memory");
}
__device__ __forceinline__ void mbar_wait_acq_cluster(uint32_t addr, uint32_t parity) {
    asm volatile(
        "{\n\t.reg .pred P;\n\t"
        "W_%=:\n\t"
        "mbarrier.try_wait.parity.acquire.cluster.shared::cta.b64 P, [%0], %1;\n\t"
        "@!P bra W_%=;\n\t}"
        :: "r"(addr), "r"(parity) : "memory");
}
__device__ __forceinline__ void mma_f16_cg2(uint32_t d_tmem, uint64_t a_desc,
                                            uint64_t b_desc, uint32_t idesc, uint32_t en) {
    asm volatile(
        "{\n\t.reg .pred p;\n\t"
        "setp.ne.u32 p, %4, 0;\n\t"
        "tcgen05.mma.cta_group::2.kind::f16 [%0], %1, %2, %3, {%5,%5,%5,%5,%5,%5,%5,%5}, p;\n\t}"
        :: "r"(d_tmem), "l"(a_desc), "l"(b_desc), "r"(idesc), "r"(en), "r"(0u) : "memory");
}
#define TCG_LD_X32(r, addr) \
    asm volatile( \
        "tcgen05.ld.sync.aligned.32x32b.x32.b32 " \
        "{%0, %1, %2, %3, %4, %5, %6, %7, " \
        " %8, %9, %10, %11, %12, %13, %14, %15, " \
        " %16, %17, %18, %19, %20, %21, %22, %23, " \
        " %24, %25, %26, %27, %28, %29, %30, %31}, [%32];" \
        : "=r"((r)[0]),  "=r"((r)[1]),  "=r"((r)[2]),  "=r"((r)[3]), \
          "=r"((r)[4]),  "=r"((r)[5]),  "=r"((r)[6]),  "=r"((r)[7]), \
          "=r"((r)[8]),  "=r"((r)[9]),  "=r"((r)[10]), "=r"((r)[11]), \
          "=r"((r)[12]), "=r"((r)[13]), "=r"((r)[14]), "=r"((r)[15]), \
          "=r"((r)[16]), "=r"((r)[17]), "=r"((r)[18]), "=r"((r)[19]), \
          "=r"((r)[20]), "=r"((r)[21]), "=r"((r)[22]), "=r"((r)[23]), \
          "=r"((r)[24]), "=r"((r)[25]), "=r"((r)[26]), "=r"((r)[27]), \
          "=r"((r)[28]), "=r"((r)[29]), "=r"((r)[30]), "=r"((r)[31]) \
        : "r"(addr))
#endif  // HAS_TCGEN05

// ---------------- convert kernels ----------------
__global__ void cvt_XW(const float* __restrict__ X, const float* __restrict__ W) {
    const size_t NX = (size_t)PIVOT * CHANNELS / 4;
    const size_t NW = (size_t)CHANNELS * CHANNELS / 4;
    size_t i = (size_t)blockIdx.x * blockDim.x + threadIdx.x;
    if (i < NX) {
        float4 f = reinterpret_cast<const float4*>(X)[i];
        __half2* o = reinterpret_cast<__half2*>(Xh_g) + i * 2;
        o[0] = __floats2half2_rn(f.x, f.y);
        o[1] = __floats2half2_rn(f.z, f.w);
    } else if (i < NX + NW) {
        size_t j = i - NX;
        float4 f = reinterpret_cast<const float4*>(W)[j];
        __half2* o = reinterpret_cast<__half2*>(Wh_g) + j * 2;
        o[0] = __floats2half2_rn(f.x, f.y);
        o[1] = __floats2half2_rn(f.z, f.w);
    }
}
// Deinterleave J: A2[2p+k][j] = J[p][2j+k]
__global__ void cvt_J(const float* __restrict__ J) {
    size_t i = (size_t)blockIdx.x * blockDim.x + threadIdx.x;  // float4 index
    size_t p = i >> 9, q = i & 511;
    float4 f = reinterpret_cast<const float4*>(J)[i];
    reinterpret_cast<__half2*>(A2_g + (2 * p) * CHANNELS)[q]     = __floats2half2_rn(f.x, f.z);
    reinterpret_cast<__half2*>(A2_g + (2 * p + 1) * CHANNELS)[q] = __floats2half2_rn(f.y, f.w);
}

// ---------------- cg2 pair-tile GEMM: 256(M) x 512(N), BK=64 ----------------
#define BMP 256
#define BN  512
#define BK  64
#define ST  3
#define KT  (CHANNELS / BK)                    // 16
#define STAGE_B 49152                          // A 16KB + B 32KB
#define CTRL    1024
#define SMEM_TOTAL (CTRL + ST * STAGE_B)       // 148480
// idesc: f32 acc (1<<4), f16 a/b, N=256 per MMA, M=256 (pair)
#define IDESC2 ((1u << 4) | (32u << 17) | (16u << 24))

// EPI: 0 = tanh(D + bias); 1 = (1-h^2)*D interleaved
template<int EPI>
__global__ void __launch_bounds__(256, 1) __cluster_dims__(2, 1, 1)
gemm2(const float* __restrict__ aux, float* __restrict__ outp)
{
#if HAS_TCGEN05
    extern __shared__ char smem[];
    const uint32_t sbase = smem_u32(smem);
    const int tid = threadIdx.x, wid = tid >> 5, lane = tid & 31;
    const uint32_t rank = ctarank();
    const int n0 = (blockIdx.x >> 1) * BN;
    const int m0 = blockIdx.y * BMP;
    const __half* __restrict__ A = (EPI == 0) ? Xh_g : A2_g;
    // mbar layout: ready[s] @ 16+8s (count 2, used on leader), done[s] @ 48+8s (count 1)
    if (wid == 0) TCG_ALLOC_CG2(sbase, 512);
    if (tid == 0) {
        #pragma unroll
        for (int s = 0; s < ST; s++) { MBAR_INIT(sbase + 16 + 8 * s, 2); MBAR_INIT(sbase + 48 + 8 * s, 1); }
    }
    __syncthreads();
    uint32_t tmem;
    asm volatile("ld.shared.b32 %0, [%1];" : "=r"(tmem) : "r"(sbase));
    CLUSTER_SYNC();

    auto load_tile = [&](int kt) {
        const int s = kt % ST;
        char* stg = smem + CTRL + s * STAGE_B;
        const int k0 = kt * BK;
        #pragma unroll
        for (int it = 0; it < 4; it++) {               // A half: 1024 chunks
            int ch = tid + it * 256;
            int r = ch >> 3, c = ch & 7;
            cp_async16(smem_u32(stg + SW128(r * 128 + c * 16)),
                       A + (size_t)(m0 + (int)rank * 128 + r) * CHANNELS + k0 + c * 8);
        }
        #pragma unroll
        for (int it = 0; it < 8; it++) {               // B (W) split: 2048 chunks
            int ch = tid + it * 256;
            int lb = ch >> 3, c = ch & 7;
            int grow = n0 + ((lb >> 7) << 8) + (int)rank * 128 + (lb & 127);
            cp_async16(smem_u32(stg + 16384 + SW128(lb * 128 + c * 16)),
                       Wh_g + (size_t)grow * CHANNELS + k0 + c * 8);
        }
        cp_commit();
    };

    load_tile(0);
    load_tile(1);

    #pragma unroll 1
    for (int kt = 0; kt < KT; kt++) {
        const int s = kt % ST;
        if (kt < KT - 1) cp_wait<1>(); else cp_wait<0>();
        __syncthreads();
        FENCE_ASYNC();
        if (tid == 0) arrive_leader(sbase + 16 + 8 * s);
        if (rank == 0 && tid == 0) {
            mbar_wait_acq_cluster(sbase + 16 + 8 * s, (uint32_t)((kt / ST) & 1));
            uint32_t stg = sbase + CTRL + s * STAGE_B;
            uint64_t ad  = make_desc(stg);
            uint64_t bd0 = make_desc(stg + 16384);
            uint64_t bd1 = make_desc(stg + 32768);
            #pragma unroll
            for (int ks = 0; ks < 4; ks++) {
                uint32_t en = (kt > 0 || ks > 0) ? 1u : 0u;
                mma_f16_cg2(tmem,       ad + 2 * ks, bd0 + 2 * ks, IDESC2, en);
                mma_f16_cg2(tmem + 256, ad + 2 * ks, bd1 + 2 * ks, IDESC2, en);
            }
            TCG_COMMIT_MC(sbase + 48 + 8 * s);
        }
        if (kt + 2 < KT) {
            if (kt >= 1)
                mbar_wait(sbase + 48 + 8 * ((kt + 2) % ST), (uint32_t)(((kt - 1) / ST) & 1));
            load_tile(kt + 2);
        }
    }
    // drain remaining done arrivals (tiles 13,14,15)
    mbar_wait(sbase + 48 + 8 * ((KT - 3) % ST), (uint32_t)(((KT - 3) / ST) & 1));
    mbar_wait(sbase + 48 + 8 * ((KT - 2) % ST), (uint32_t)(((KT - 2) / ST) & 1));
    mbar_wait(sbase + 48 + 8 * ((KT - 1) % ST), (uint32_t)(((KT - 1) / ST) & 1));
    TCG_FENCE_AFTER();
    __syncthreads();

    const int sub = wid & 3, cb = (wid >> 2) * 256;

    if (EPI == 0) {
        float* bs = reinterpret_cast<float*>(smem + CTRL);       // 512 floats
        bs[tid] = aux[n0 + tid];
        bs[tid + 256] = aux[n0 + 256 + tid];
        __syncthreads();
        const int row = m0 + (int)rank * 128 + sub * 32 + lane;
        #pragma unroll 1
        for (int cc = 0; cc < 8; cc++) {
            uint32_t d[32];
            TCG_LD_X32(d, tmem + cb + cc * 32);
            TCG_WAIT_LD();
            float* orow = outp + (size_t)row * CHANNELS + n0 + cb + cc * 32;
            #pragma unroll
            for (int j = 0; j < 32; j += 4) {
                float4 o;
                o.x = tanhf(__uint_as_float(d[j + 0]) + bs[cb + cc * 32 + j + 0]);
                o.y = tanhf(__uint_as_float(d[j + 1]) + bs[cb + cc * 32 + j + 1]);
                o.z = tanhf(__uint_as_float(d[j + 2]) + bs[cb + cc * 32 + j + 2]);
                o.w = tanhf(__uint_as_float(d[j + 3]) + bs[cb + cc * 32 + j + 3]);
                *reinterpret_cast<float4*>(orow + j) = o;
            }
        }
    } else {
        // stage h tile: 64 p-rows x 512 cols, stride 516 floats (132KB, reuses stages)
        float* hs = reinterpret_cast<float*>(smem + CTRL);
        const int pbase = (m0 + (int)rank * 128) >> 1;
        #pragma unroll
        for (int it = 0; it < 32; it++) {
            int idx = tid + it * 256;               // 8192 float4
            int pr = idx >> 7, c4 = (idx & 127) * 4;
            float4 v = *reinterpret_cast<const float4*>(
                aux + (size_t)(pbase + pr) * CHANNELS + n0 + c4);
            *reinterpret_cast<float4*>(hs + pr * 516 + c4) = v;
        }
        __syncthreads();
        const int v = sub * 32 + lane;              // local virtual row (0..127)
        const int pl = v >> 1;
        const float* hrow = hs + pl * 516;
        float* obase = outp + (size_t)(pbase + pl) * 2048 + 2 * (size_t)n0;
        #pragma unroll 1
        for (int cc = 0; cc < 8; cc++) {
            uint32_t d[32];
            TCG_LD_X32(d, tmem + cb + cc * 32);
            TCG_WAIT_LD();
            #pragma unroll
            for (int j = 0; j < 32; j++) {
                int cl = cb + cc * 32 + j;
                float hv = hrow[cl];
                float r = (1.f - hv * hv) * __uint_as_float(d[j]);
                float other = __shfl_xor_sync(0xFFFFFFFFu, r, 1);
                if ((lane & 1) == 0)
                    *reinterpret_cast<float2*>(obase + 2 * cl) = make_float2(r, other);
            }
        }
    }

    TCG_FENCE_BEFORE();
    __syncthreads();
    CLUSTER_SYNC();
    if (tid == 0) {
        #pragma unroll
        for (int s = 0; s < ST; s++) { MBAR_INVAL(sbase + 16 + 8 * s); MBAR_INVAL(sbase + 48 + 8 * s); }
    }
    __syncthreads();
    if (wid == 0) { TCG_RELINQ_CG2(); TCG_DEALLOC_CG2(tmem, 512); }
    CLUSTER_SYNC();

#else  // ---------- non-sm_103a fallback (never runs on GB300) ----------
    const int tid = threadIdx.x;
    const int rank = blockIdx.x & 1;
    const int n0 = (blockIdx.x >> 1) * BN;
    const int m0 = blockIdx.y * BMP + rank * 128;
    const __half* __restrict__ A = (EPI == 0) ? Xh_g : A2_g;
    for (int idx = tid; idx < 128 * BN; idx += blockDim.x) {
        int mi = idx >> 9, ni = idx & 511;
        int m = m0 + mi, n = n0 + ni;
        float acc = 0.f;
        for (int k = 0; k < CHANNELS; k++)
            acc += __half2float(A[(size_t)m * CHANNELS + k]) *
                   __half2float(Wh_g[(size_t)n * CHANNELS + k]);
        if (EPI == 0) {
            outp[(size_t)m * CHANNELS + n] = tanhf(acc + aux[n]);
        } else {
            int p = m >> 1, kb = m & 1;
            float hv = aux[(size_t)p * CHANNELS + n];
            outp[(size_t)p * 2048 + 2 * (size_t)n + kb] = (1.f - hv * hv) * acc;
        }
    }
#endif
}

// ---------------- launcher ----------------
extern "C" void kernel_launch(void* const* d_in, const int* in_sizes, int n_in,
                              void* d_out, int out_size)
{
    const float* x = (const float*)d_in[0];   // [3*PIVOT, CHANNELS]
    const float* W = (const float*)d_in[1];   // [CHANNELS, CHANNELS]
    const float* b = (const float*)d_in[2];   // [CHANNELS]
    float* out = (float*)d_out;

    cudaFuncSetAttribute(gemm2<0>, cudaFuncAttributeMaxDynamicSharedMemorySize, SMEM_TOTAL);
    cudaFuncSetAttribute(gemm2<1>, cudaFuncAttributeMaxDynamicSharedMemorySize, SMEM_TOTAL);

    const size_t NX = (size_t)PIVOT * CHANNELS / 4;
    const size_t NW = (size_t)CHANNELS * CHANNELS / 4;
    cvt_XW<<<(unsigned)((NX + NW) / 256), 256>>>(x, W);
    cvt_J<<<(unsigned)((size_t)PIVOT * 512 / 256), 256>>>(x + (size_t)PIVOT * CHANNELS);

    dim3 g1(2 * (CHANNELS / BN), PIVOT / BMP);          // (4, 64)
    gemm2<0><<<g1, 256, SMEM_TOTAL>>>(b, out);

    dim3 g2(2 * (CHANNELS / BN), (2 * PIVOT) / BMP);    // (4, 128)
    gemm2<1><<<g2, 256, SMEM_TOTAL>>>(out, out + (size_t)PIVOT * CHANNELS);
}

// round 6
// speedup vs baseline: 1.3765x; 1.3765x over previous
#include <cuda_runtime.h>
#include <cuda_fp16.h>
#include <cuda.h>
#include <cstdint>
#include <cstddef>

#define CHANNELS 1024
#define PIVOT 16384

// tcgen05/TMA are arch-SPECIFIC. The harness also compiles a non-'a'
// compute_103 PTX pass; give it a plain-CUDA fallback body.
#if defined(__CUDA_ARCH_FEAT_SM103_ALL) || defined(__CUDA_ARCH_FEAT_SM100_ALL) || defined(__CUDA_ARCH_SPECIFIC__)
#define HAS_TCGEN05 1
#else
#define HAS_TCGEN05 0
#endif

// ---------------- scratch (static device arrays are allowed) ----------
__device__ __align__(1024) __half Xh_g[(size_t)PIVOT * CHANNELS];        // 32 MB
__device__ __align__(1024) __half Wh_g[(size_t)CHANNELS * CHANNELS];     //  2 MB
__device__ __align__(1024) __half A2_g[(size_t)2 * PIVOT * CHANNELS];    // 64 MB

// ---------------- device helpers ----------------
__device__ __forceinline__ uint32_t smem_u32(const void* p) {
    uint32_t r;
    asm("{ .reg .u64 t; cvta.to.shared.u64 t, %1; cvt.u32.u64 %0, t; }" : "=r"(r) : "l"(p));
    return r;
}
__device__ __forceinline__ uint32_t elect_one() {
    uint32_t p;
    asm volatile("{ .reg .pred p; elect.sync _|p, 0xFFFFFFFF; selp.b32 %0, 1, 0, p; }" : "=r"(p));
    return p;
}
// SW128 K-major smem descriptor (layout=2, version=1, SBO=64, LBO=1)
__device__ __forceinline__ uint64_t make_desc(uint32_t addr) {
    const uint64_t base = (uint64_t(2) << 61) | (uint64_t(1) << 46)
                        | (uint64_t(64) << 32) | (uint64_t(1) << 16);
    return base | ((uint64_t)(addr >> 4) & 0x3FFF);
}

#if HAS_TCGEN05
#define TCG_ALLOC(smem_res, ncols) \
    asm volatile("tcgen05.alloc.cta_group::1.sync.aligned.shared::cta.b32 [%0], %1;" \
                 :: "r"(smem_res), "r"((uint32_t)(ncols)) : "memory")
#define TCG_RELINQ() \
    asm volatile("tcgen05.relinquish_alloc_permit.cta_group::1.sync.aligned;")
#define TCG_DEALLOC(tmem, ncols) \
    asm volatile("tcgen05.dealloc.cta_group::1.sync.aligned.b32 %0, %1;" \
                 :: "r"(tmem), "r"((uint32_t)(ncols)))
#define TCG_COMMIT(mbar) \
    asm volatile("tcgen05.commit.cta_group::1.mbarrier::arrive::one.shared::cluster.b64 [%0];" \
                 :: "r"(mbar) : "memory")
#define TCG_FENCE_AFTER()  asm volatile("tcgen05.fence::after_thread_sync;" ::: "memory")
#define TCG_FENCE_BEFORE() asm volatile("tcgen05.fence::before_thread_sync;" ::: "memory")
#define TCG_WAIT_LD()      asm volatile("tcgen05.wait::ld.sync.aligned;" ::: "memory")
#define FENCE_ASYNC()      asm volatile("fence.proxy.async.shared::cta;" ::: "memory")
#define MBAR_INIT(addr, cnt) \
    asm volatile("mbarrier.init.shared.b64 [%0], %1;" :: "r"(addr), "r"((uint32_t)(cnt)) : "memory")
#define MBAR_INVAL(addr) \
    asm volatile("mbarrier.inval.shared.b64 [%0];" :: "r"(addr) : "memory")
#define MBAR_EXPECT_TX(addr, bytes) \
    asm volatile("mbarrier.arrive.expect_tx.shared.b64 _, [%0], %1;" \
                 :: "r"(addr), "r"((uint32_t)(bytes)) : "memory")

__device__ __forceinline__ void mbar_wait(uint32_t addr, uint32_t parity) {
    asm volatile(
        "{\n\t.reg .pred P;\n\t"
        "W_%=:\n\t"
        "mbarrier.try_wait.parity.shared.b64 P, [%0], %1;\n\t"
        "@!P bra W_%=;\n\t}"
        :: "r"(addr), "r"(parity) : "memory");
}
__device__ __forceinline__ void tma2d(uint32_t dst, const void* map,
                                      int32_t cx, int32_t cy, uint32_t mbar) {
    asm volatile(
        "cp.async.bulk.tensor.2d.shared::cta.global.tile.mbarrier::complete_tx::bytes "
        "[%0], [%1, {%2, %3}], [%4];"
        :: "r"(dst), "l"(map), "r"(cx), "r"(cy), "r"(mbar) : "memory");
}
__device__ __forceinline__ void mma_f16_ss(uint32_t d_tmem, uint64_t a_desc,
                                           uint64_t b_desc, uint32_t idesc, uint32_t en) {
    asm volatile(
        "{\n\t.reg .pred p;\n\t"
        "setp.ne.u32 p, %4, 0;\n\t"
        "tcgen05.mma.cta_group::1.kind::f16 [%0], %1, %2, %3, {%5,%5,%5,%5}, p;\n\t}"
        :: "r"(d_tmem), "l"(a_desc), "l"(b_desc), "r"(idesc), "r"(en), "r"(0u) : "memory");
}
#define TCG_LD_X32(r, addr) \
    asm volatile( \
        "tcgen05.ld.sync.aligned.32x32b.x32.b32 " \
        "{%0, %1, %2, %3, %4, %5, %6, %7, " \
        " %8, %9, %10, %11, %12, %13, %14, %15, " \
        " %16, %17, %18, %19, %20, %21, %22, %23, " \
        " %24, %25, %26, %27, %28, %29, %30, %31}, [%32];" \
        : "=r"((r)[0]),  "=r"((r)[1]),  "=r"((r)[2]),  "=r"((r)[3]), \
          "=r"((r)[4]),  "=r"((r)[5]),  "=r"((r)[6]),  "=r"((r)[7]), \
          "=r"((r)[8]),  "=r"((r)[9]),  "=r"((r)[10]), "=r"((r)[11]), \
          "=r"((r)[12]), "=r"((r)[13]), "=r"((r)[14]), "=r"((r)[15]), \
          "=r"((r)[16]), "=r"((r)[17]), "=r"((r)[18]), "=r"((r)[19]), \
          "=r"((r)[20]), "=r"((r)[21]), "=r"((r)[22]), "=r"((r)[23]), \
          "=r"((r)[24]), "=r"((r)[25]), "=r"((r)[26]), "=r"((r)[27]), \
          "=r"((r)[28]), "=r"((r)[29]), "=r"((r)[30]), "=r"((r)[31]) \
        : "r"(addr))
#endif  // HAS_TCGEN05

// ---------------- convert kernels ----------------
__global__ void cvt_XW(const float* __restrict__ X, const float* __restrict__ W) {
    const size_t NX = (size_t)PIVOT * CHANNELS / 4;
    const size_t NW = (size_t)CHANNELS * CHANNELS / 4;
    size_t i = (size_t)blockIdx.x * blockDim.x + threadIdx.x;
    if (i < NX) {
        float4 f = reinterpret_cast<const float4*>(X)[i];
        __half2* o = reinterpret_cast<__half2*>(Xh_g) + i * 2;
        o[0] = __floats2half2_rn(f.x, f.y);
        o[1] = __floats2half2_rn(f.z, f.w);
    } else if (i < NX + NW) {
        size_t j = i - NX;
        float4 f = reinterpret_cast<const float4*>(W)[j];
        __half2* o = reinterpret_cast<__half2*>(Wh_g) + j * 2;
        o[0] = __floats2half2_rn(f.x, f.y);
        o[1] = __floats2half2_rn(f.z, f.w);
    }
}
// Deinterleave J: A2[2p+k][j] = J[p][2j+k]
__global__ void cvt_J(const float* __restrict__ J) {
    size_t i = (size_t)blockIdx.x * blockDim.x + threadIdx.x;  // float4 index
    size_t p = i >> 9, q = i & 511;
    float4 f = reinterpret_cast<const float4*>(J)[i];
    reinterpret_cast<__half2*>(A2_g + (2 * p) * CHANNELS)[q]     = __floats2half2_rn(f.x, f.z);
    reinterpret_cast<__half2*>(A2_g + (2 * p + 1) * CHANNELS)[q] = __floats2half2_rn(f.y, f.w);
}

// ---------------- TMA-fed tcgen05 GEMM: 256x256x64, 3 stages ----------------
#define BM 256
#define BN 256
#define BK 64
#define ST 3
#define KT (CHANNELS / BK)                   // 16
#define STAGE_B 65536                        // A 32KB + B 32KB
#define STAGES0 4096
#define SMEM_TOTAL (STAGES0 + ST * STAGE_B)  // 200704
// idesc: f32 acc (1<<4), f16 a/b, N=256 -> (N/8)<<17, M=128 -> (M/16)<<24
#define IDESC ((1u << 4) | (32u << 17) | (8u << 24))
// ctrl smem: [0,4) tmem ptr; full[s] @ 16+8s; done[s] @ 48+8s; fin @ 80; bias @ 1024

template<int EPI>
__global__ void __launch_bounds__(256, 1) gemm_tma(
    const __grid_constant__ CUtensorMap mapA,
    const __grid_constant__ CUtensorMap mapB,
    const __half* __restrict__ Araw, const __half* __restrict__ Wraw,
    const float* __restrict__ aux,   // EPI0: bias; EPI1: h = out[0:PIVOT]
    float* __restrict__ outp)        // EPI0: out;  EPI1: out2
{
#if HAS_TCGEN05
    extern __shared__ char smem[];
    const uint32_t sbase = smem_u32(smem);
    const int tid = threadIdx.x, wid = tid >> 5, lane = tid & 31;
    const int m0 = blockIdx.y * BM, n0 = blockIdx.x * BN;

    if (wid == 0) { TCG_ALLOC(sbase, 512); TCG_RELINQ(); }
    if (tid == 0) {
        #pragma unroll
        for (int s = 0; s < ST; s++) { MBAR_INIT(sbase + 16 + 8 * s, 1); MBAR_INIT(sbase + 48 + 8 * s, 1); }
        MBAR_INIT(sbase + 80, 1);
    }
    __syncthreads();
    uint32_t tmem;
    asm volatile("ld.shared.b32 %0, [%1];" : "=r"(tmem) : "r"(sbase));

    if (wid == 1) {
        // -------- TMA producer warp --------
        auto issue = [&](int kt) {
            const int s = kt % ST;
            const uint32_t stg = sbase + STAGES0 + s * STAGE_B;
            const uint32_t fb  = sbase + 16 + 8 * s;
            if (lane == 0) {
                MBAR_EXPECT_TX(fb, STAGE_B);
                tma2d(stg,         &mapA, kt * BK, m0, fb);
                tma2d(stg + 32768, &mapB, kt * BK, n0, fb);
            }
        };
        issue(0); issue(1); issue(2);
        #pragma unroll 1
        for (int kt = 0; kt + 3 < KT; kt++) {
            mbar_wait(sbase + 48 + 8 * (kt % ST), (uint32_t)((kt / ST) & 1));
            issue(kt + 3);
        }
    } else if (wid == 0) {
        // -------- MMA consumer warp --------
        #pragma unroll 1
        for (int kt = 0; kt < KT; kt++) {
            const int s = kt % ST;
            mbar_wait(sbase + 16 + 8 * s, (uint32_t)((kt / ST) & 1));
            if (elect_one()) {
                const uint32_t stg = sbase + STAGES0 + s * STAGE_B;
                uint64_t ad = make_desc(stg);
                uint64_t bd = make_desc(stg + 32768);
                #pragma unroll
                for (int ks = 0; ks < 4; ks++) {
                    uint32_t en = (kt > 0 || ks > 0) ? 1u : 0u;
                    mma_f16_ss(tmem,       ad + 2 * ks,        bd + 2 * ks, IDESC, en);
                    mma_f16_ss(tmem + 256, ad + 1024 + 2 * ks, bd + 2 * ks, IDESC, en);
                }
                TCG_COMMIT((kt < KT - 1) ? (sbase + 48 + 8 * s) : (sbase + 80));
            }
        }
    }

    // -------- all threads: wait for final MMA --------
    mbar_wait(sbase + 80, 0);
    TCG_FENCE_AFTER();
    FENCE_ASYNC();          // generic-proxy writes below into TMA-written smem
    __syncthreads();

    const int half = wid >> 2, sub = wid & 3;

    if (EPI == 0) {
        float* bs = reinterpret_cast<float*>(smem + 1024);   // 256 floats
        bs[tid] = aux[n0 + tid];
        __syncthreads();
        const int row = m0 + half * 128 + sub * 32 + lane;
        #pragma unroll 1
        for (int cc = 0; cc < 8; cc++) {
            uint32_t d[32];
            TCG_LD_X32(d, tmem + half * 256 + cc * 32);
            TCG_WAIT_LD();
            float* orow = outp + (size_t)row * CHANNELS + n0 + cc * 32;
            #pragma unroll
            for (int j = 0; j < 32; j += 4) {
                float4 o;
                o.x = tanhf(__uint_as_float(d[j + 0]) + bs[cc * 32 + j + 0]);
                o.y = tanhf(__uint_as_float(d[j + 1]) + bs[cc * 32 + j + 1]);
                o.z = tanhf(__uint_as_float(d[j + 2]) + bs[cc * 32 + j + 2]);
                o.w = tanhf(__uint_as_float(d[j + 3]) + bs[cc * 32 + j + 3]);
                *reinterpret_cast<float4*>(orow + j) = o;
            }
        }
    } else {
        // stage h tile: 128 p-rows x 256 cols, stride 260 floats (133 KB in stage area)
        float* hs = reinterpret_cast<float*>(smem + STAGES0);
        const int p0 = m0 >> 1;
        #pragma unroll
        for (int it = 0; it < 32; it++) {
            int idx = tid + it * 256;                 // 8192 float4
            int pr = idx >> 6, c4 = (idx & 63) * 4;
            float4 v = *reinterpret_cast<const float4*>(
                aux + (size_t)(p0 + pr) * CHANNELS + n0 + c4);
            *reinterpret_cast<float4*>(hs + pr * 260 + c4) = v;
        }
        __syncthreads();
        const int v = half * 128 + sub * 32 + lane;   // virtual row in tile
        const int pl = v >> 1;
        const float* hrow = hs + pl * 260;
        float* obase = outp + (size_t)(p0 + pl) * 2048 + 2 * (size_t)n0;
        #pragma unroll 1
        for (int cc = 0; cc < 8; cc++) {
            uint32_t d[32];
            TCG_LD_X32(d, tmem + half * 256 + cc * 32);
            TCG_WAIT_LD();
            #pragma unroll
            for (int j = 0; j < 32; j++) {
                int cl = cc * 32 + j;
                float hv = hrow[cl];
                float r = (1.f - hv * hv) * __uint_as_float(d[j]);
                float other = __shfl_xor_sync(0xFFFFFFFFu, r, 1);
                if ((lane & 1) == 0)
                    *reinterpret_cast<float2*>(obase + 2 * cl) = make_float2(r, other);
            }
        }
    }

    TCG_FENCE_BEFORE();
    __syncthreads();
    if (tid == 0) {
        #pragma unroll
        for (int s = 0; s < ST; s++) { MBAR_INVAL(sbase + 16 + 8 * s); MBAR_INVAL(sbase + 48 + 8 * s); }
        MBAR_INVAL(sbase + 80);
    }
    __syncthreads();
    if (wid == 0) TCG_DEALLOC(tmem, 512);

#else  // ---------- non-sm_103a fallback (never runs on GB300) ----------
    const int tid = threadIdx.x;
    const int m0 = blockIdx.y * BM, n0 = blockIdx.x * BN;
    for (int idx = tid; idx < BM * BN; idx += blockDim.x) {
        int mi = idx >> 8, ni = idx & 255;
        int m = m0 + mi, n = n0 + ni;
        float acc = 0.f;
        for (int k = 0; k < CHANNELS; k++)
            acc += __half2float(Araw[(size_t)m * CHANNELS + k]) *
                   __half2float(Wraw[(size_t)n * CHANNELS + k]);
        if (EPI == 0) {
            outp[(size_t)m * CHANNELS + n] = tanhf(acc + aux[n]);
        } else {
            int p = m >> 1, kb = m & 1;
            float hv = aux[(size_t)p * CHANNELS + n];
            outp[(size_t)p * 2048 + 2 * (size_t)n + kb] = (1.f - hv * hv) * acc;
        }
    }
#endif
}

// ---------------- host launcher ----------------
typedef CUresult (*tmap_encode_fn)(
    CUtensorMap*, CUtensorMapDataType, cuuint32_t, void*,
    const cuuint64_t*, const cuuint64_t*, const cuuint32_t*, const cuuint32_t*,
    CUtensorMapInterleave, CUtensorMapSwizzle, CUtensorMapL2promotion,
    CUtensorMapFloatOOBfill);

static void make_map2d(tmap_encode_fn enc, CUtensorMap* m, void* base, unsigned long long rows) {
    cuuint64_t dims[2]    = {(cuuint64_t)CHANNELS, (cuuint64_t)rows};
    cuuint64_t strides[1] = {(cuuint64_t)(CHANNELS * sizeof(__half))};
    cuuint32_t box[2]     = {64u, 256u};
    cuuint32_t es[2]      = {1u, 1u};
    enc(m, CU_TENSOR_MAP_DATA_TYPE_FLOAT16, 2, base, dims, strides, box, es,
        CU_TENSOR_MAP_INTERLEAVE_NONE, CU_TENSOR_MAP_SWIZZLE_128B,
        CU_TENSOR_MAP_L2_PROMOTION_L2_128B, CU_TENSOR_MAP_FLOAT_OOB_FILL_NONE);
}

extern "C" void kernel_launch(void* const* d_in, const int* in_sizes, int n_in,
                              void* d_out, int out_size)
{
    const float* x = (const float*)d_in[0];   // [3*PIVOT, CHANNELS]
    const float* W = (const float*)d_in[1];   // [CHANNELS, CHANNELS]
    const float* b = (const float*)d_in[2];   // [CHANNELS]
    float* out = (float*)d_out;

    void *pX = nullptr, *pW = nullptr, *pA2 = nullptr;
    cudaGetSymbolAddress(&pX,  Xh_g);
    cudaGetSymbolAddress(&pW,  Wh_g);
    cudaGetSymbolAddress(&pA2, A2_g);

    void* encp = nullptr;
    cudaDriverEntryPointQueryResult qr;
    cudaGetDriverEntryPoint("cuTensorMapEncodeTiled", &encp, cudaEnableDefault, &qr);
    tmap_encode_fn enc = (tmap_encode_fn)encp;

    CUtensorMap mX, mW, mA2;
    make_map2d(enc, &mX,  pX,  PIVOT);
    make_map2d(enc, &mW,  pW,  CHANNELS);
    make_map2d(enc, &mA2, pA2, 2 * PIVOT);

    cudaFuncSetAttribute(gemm_tma<0>, cudaFuncAttributeMaxDynamicSharedMemorySize, SMEM_TOTAL);
    cudaFuncSetAttribute(gemm_tma<1>, cudaFuncAttributeMaxDynamicSharedMemorySize, SMEM_TOTAL);

    const size_t NX = (size_t)PIVOT * CHANNELS / 4;
    const size_t NW = (size_t)CHANNELS * CHANNELS / 4;
    cvt_XW<<<(unsigned)((NX + NW) / 256), 256>>>(x, W);
    cvt_J<<<(unsigned)((size_t)PIVOT * 512 / 256), 256>>>(x + (size_t)PIVOT * CHANNELS);

    dim3 g1(CHANNELS / BN, PIVOT / BM);          // (4, 64)
    gemm_tma<0><<<g1, 256, SMEM_TOTAL>>>(mX, mW, (const __half*)pX, (const __half*)pW, b, out);

    dim3 g2(CHANNELS / BN, (2 * PIVOT) / BM);    // (4, 128)
    gemm_tma<1><<<g2, 256, SMEM_TOTAL>>>(mA2, mW, (const __half*)pA2, (const __half*)pW,
                                         out, out + (size_t)PIVOT * CHANNELS);
}